// round 7
// baseline (speedup 1.0000x reference)
#include <cuda_runtime.h>
#include <cuda_bf16.h>
#include <math.h>

#define NFR    65536
#define DIM    512
#define HEADS  8
#define ATTR   256
#define XDIM   768
#define KSTEPS 16
#define SCALE  0.125f
#define NSTREAM 296
#define GRIDA  148
#define WPAD   152          // padded partial-count per (h,c) row

// ------------------------- static device scratch -------------------------
__device__ __align__(16) __nv_bfloat16 g_Fh[NFR*DIM];    // bf16 frames (64MB)
__device__ __align__(16) float g_WckT[DIM*DIM];          // scale*(W_ctx@Wk)^T [o][i]
__device__ __align__(16) float g_Wcv [DIM*DIM];          // W_ctx@Wv [i][o]
__device__ __align__(16) float g_A[HEADS*DIM*DIM];       // A_h = WckT_h @ Wq_h^T (8MB)
__device__ __align__(16) float g_Wih2[1536*XDIM];        // [W_ih[:,:256] | W_ih[:,256:]@Wo^T]
__device__ __align__(16) float g_bih2[1536];
__device__ __align__(16) float g_cvec[HEADS*DIM];
__device__ __align__(16) float g_cspart[1024*DIM];       // per-block colsum partials
__device__ __align__(16) float g_colsum[DIM];
__device__ __align__(16) float g_bvp[DIM];
__device__ __align__(16) float g_h[2][DIM];
__device__ __align__(16) float g_u[HEADS*DIM];           // [h][i]
__device__ __align__(16) float g_x[XDIM];                // [a_prev(256); vraw(512)]
__device__ __align__(16) float g_ihh[3072];
__device__ __align__(16) float g_wpartT[HEADS*DIM*WPAD]; // [(h*512+c)*WPAD + block]
__device__ float g_spart[GRIDA*HEADS];
__device__ float g_mpart[GRIDA*HEADS];

__device__ __forceinline__ float wred(float a){
    #pragma unroll
    for (int o = 16; o; o >>= 1) a += __shfl_xor_sync(0xffffffffu, a, o);
    return a;
}
// ---- packed fp32 (f32x2) helpers ----
typedef unsigned long long ull;
#define FMA2(d,a,b) asm("fma.rn.f32x2 %0, %1, %2, %0;" : "+l"(d) : "l"(a), "l"(b))
#define MUL2(d,a,b) asm("mul.rn.f32x2 %0, %1, %2;" : "=l"(d) : "l"(a), "l"(b))
__device__ __forceinline__ ull fpack(float a, float b){
    ull r; asm("mov.b64 %0, {%1, %2};" : "=l"(r) : "f"(a), "f"(b)); return r;
}
__device__ __forceinline__ ull bfp(unsigned w){
    unsigned lo = w << 16, hi = w & 0xffff0000u;
    ull r; asm("mov.b64 %0, {%1, %2};" : "=l"(r) : "r"(lo), "r"(hi)); return r;
}
__device__ __forceinline__ float2 funp(ull v){
    float x, y; asm("mov.b64 {%0, %1}, %2;" : "=f"(x), "=f"(y) : "l"(v));
    return make_float2(x, y);
}

// ------------------------------ setup ------------------------------------
// F -> bf16 + per-block colsum partials. grid 1024 x 256.
__global__ void p1c(const float4* __restrict__ F4){
    const int tid = threadIdx.x, col = tid & 127, rh = tid >> 7;
    const int r0 = blockIdx.x*64;
    float4 acc = make_float4(0.f,0.f,0.f,0.f);
    uint2* out = (uint2*)g_Fh;
    for (int i = 0; i < 32; i++){
        size_t row = r0 + i*2 + rh;
        float4 f = F4[row*128 + col];
        acc.x += f.x; acc.y += f.y; acc.z += f.z; acc.w += f.w;
        uint2 pk;
        pk.x = ((unsigned)__bfloat16_as_ushort(__float2bfloat16_rn(f.y)) << 16)
             |  (unsigned)__bfloat16_as_ushort(__float2bfloat16_rn(f.x));
        pk.y = ((unsigned)__bfloat16_as_ushort(__float2bfloat16_rn(f.w)) << 16)
             |  (unsigned)__bfloat16_as_ushort(__float2bfloat16_rn(f.z));
        out[row*128 + col] = pk;
    }
    __shared__ float cs[512];
    if (rh == 0){
        cs[col*4+0]=acc.x; cs[col*4+1]=acc.y; cs[col*4+2]=acc.z; cs[col*4+3]=acc.w;
    }
    __syncthreads();
    if (rh == 1){
        size_t b = (size_t)blockIdx.x*512 + col*4;
        g_cspart[b+0] = cs[col*4+0]+acc.x;
        g_cspart[b+1] = cs[col*4+1]+acc.y;
        g_cspart[b+2] = cs[col*4+2]+acc.z;
        g_cspart[b+3] = cs[col*4+3]+acc.w;
    }
}

// z=0: WckT = scale*(W_ctx@Wk)^T ; z=1: Wcv = W_ctx@Wv ; z=2: colsum reduce
__global__ void p2(const float* __restrict__ Wctx,
                   const float* __restrict__ Wk,
                   const float* __restrict__ Wv){
    if (blockIdx.z == 2){
        if (blockIdx.y != 0) return;
        const int tid = threadIdx.y*32 + threadIdx.x;
        const int col = blockIdx.x*32 + (tid & 31), seg = tid >> 5;
        float a = 0.f;
        #pragma unroll 8
        for (int p = seg*128; p < seg*128+128; p++) a += g_cspart[(size_t)p*512 + col];
        __shared__ float sr[8][33];
        sr[seg][tid & 31] = a;
        __syncthreads();
        if (tid < 32){
            float s2 = 0.f;
            #pragma unroll
            for (int q = 0; q < 8; q++) s2 += sr[q][tid];
            g_colsum[blockIdx.x*32 + tid] = s2;
        }
        return;
    }
    __shared__ float sA[32][33];
    __shared__ float sB[32][33];
    int tx = threadIdx.x, ty = threadIdx.y;
    const float* B = blockIdx.z ? Wv : Wk;
    int i0 = blockIdx.y*32, j0 = blockIdx.x*32;
    float acc[4] = {0.f,0.f,0.f,0.f};
    for (int m0 = 0; m0 < DIM; m0 += 32){
        #pragma unroll
        for (int k = 0; k < 4; k++){
            sA[ty+8*k][tx] = Wctx[(size_t)(i0+ty+8*k)*DIM + m0+tx];
            sB[ty+8*k][tx] = B[(size_t)(m0+ty+8*k)*DIM + j0+tx];
        }
        __syncthreads();
        #pragma unroll
        for (int mm = 0; mm < 32; mm++){
            float b = sB[mm][tx];
            #pragma unroll
            for (int k = 0; k < 4; k++) acc[k] += sA[ty+8*k][mm]*b;
        }
        __syncthreads();
    }
    if (blockIdx.z){
        #pragma unroll
        for (int k = 0; k < 4; k++)
            g_Wcv[(size_t)(i0+ty+8*k)*DIM + j0+tx] = acc[k];
    } else {
        __syncthreads();
        #pragma unroll
        for (int k = 0; k < 4; k++) sA[tx][ty+8*k] = acc[k];
        __syncthreads();
        #pragma unroll
        for (int k = 0; k < 4; k++)
            g_WckT[(size_t)(j0+ty+8*k)*DIM + i0+tx] = SCALE*sA[ty+8*k][tx];
    }
}

// z<8: A_h[i][j] = sum_d WckT[h*64+d][i]*Wq[j][h*64+d] ; z=8: Wih2 build
__global__ __launch_bounds__(256) void pAB(const float* __restrict__ Wq,
                                           const float* __restrict__ W_ih,
                                           const float* __restrict__ Wo){
    const int tid = threadIdx.x;
    const int z = blockIdx.z;
    if (z < 8){
        if (blockIdx.y >= 16) return;
        __shared__ float sA_[32][65];
        __shared__ float sB_[32][65];
        const int h = z, i0 = blockIdx.y*32, j0 = blockIdx.x*32;
        for (int e = tid; e < 2048; e += 256){
            int r = e & 31, d = e >> 5;
            sA_[r][d] = g_WckT[(size_t)(h*64+d)*DIM + i0 + r];
        }
        for (int e = tid; e < 2048; e += 256){
            int rj = e >> 6, d = e & 63;
            sB_[rj][d] = Wq[(size_t)(j0+rj)*DIM + h*64 + d];
        }
        __syncthreads();
        const int tx = tid & 31, ty = tid >> 5;
        float acc[4] = {0.f,0.f,0.f,0.f};
        #pragma unroll 8
        for (int d = 0; d < 64; d++){
            float bb = sB_[tx][d];
            #pragma unroll
            for (int k = 0; k < 4; k++) acc[k] += sA_[ty+8*k][d]*bb;
        }
        #pragma unroll
        for (int k = 0; k < 4; k++)
            g_A[(size_t)(h*DIM + i0+ty+8*k)*DIM + j0+tx] = acc[k];
    } else {
        const int i0 = blockIdx.y*64;
        if (blockIdx.x < 8){
            __shared__ float sA[64][33];
            __shared__ float sB[64][33];
            const int j0 = blockIdx.x*64;
            const int tx = tid & 15, ty = tid >> 4;
            float acc[4][4];
            #pragma unroll
            for (int a = 0; a < 4; a++)
                #pragma unroll
                for (int b = 0; b < 4; b++) acc[a][b] = 0.f;
            for (int m0 = 0; m0 < DIM; m0 += 32){
                #pragma unroll
                for (int q = 0; q < 2; q++){
                    int e = tid + q*256, r = e >> 3, c = e & 7;
                    float4 va = *(const float4*)(W_ih + (size_t)(i0+r)*XDIM + 256 + m0 + c*4);
                    sA[r][c*4+0]=va.x; sA[r][c*4+1]=va.y; sA[r][c*4+2]=va.z; sA[r][c*4+3]=va.w;
                    float4 vb = *(const float4*)(Wo + (size_t)(j0+r)*DIM + m0 + c*4);
                    sB[r][c*4+0]=vb.x; sB[r][c*4+1]=vb.y; sB[r][c*4+2]=vb.z; sB[r][c*4+3]=vb.w;
                }
                __syncthreads();
                #pragma unroll
                for (int m = 0; m < 32; m++){
                    float a4[4], b4[4];
                    #pragma unroll
                    for (int k = 0; k < 4; k++){ a4[k] = sA[ty*4+k][m]; b4[k] = sB[tx*4+k][m]; }
                    #pragma unroll
                    for (int a = 0; a < 4; a++)
                        #pragma unroll
                        for (int b = 0; b < 4; b++) acc[a][b] += a4[a]*b4[b];
                }
                __syncthreads();
            }
            #pragma unroll
            for (int a = 0; a < 4; a++){
                float4 v = make_float4(acc[a][0], acc[a][1], acc[a][2], acc[a][3]);
                *(float4*)(g_Wih2 + (size_t)(i0+ty*4+a)*XDIM + 256 + j0 + tx*4) = v;
            }
        } else if (blockIdx.x < 12){
            const int c0 = (blockIdx.x-8)*64;
            for (int e = tid; e < 64*16; e += 256){
                int r = e >> 4, c = e & 15;
                *(float4*)(g_Wih2 + (size_t)(i0+r)*XDIM + c0 + c*4) =
                    *(const float4*)(W_ih + (size_t)(i0+r)*XDIM + c0 + c*4);
            }
        }
    }
}

// parallel vectors: bvp (b<8), h0 (b<16), cvec (b<24)
__global__ void p4v(const float* __restrict__ Wctx, const float* __restrict__ bctx,
                    const float* __restrict__ bq,   const float* __restrict__ Wv,
                    const float* __restrict__ bv){
    const int b = blockIdx.x, tid = threadIdx.x;
    __shared__ float sp[4][64];
    const int tc = tid & 63, pc = tid >> 6;
    if (b < 8){
        const int t = b*64 + tc;
        float a = 0.f;
        #pragma unroll 4
        for (int i = pc*128; i < pc*128+128; i++) a += bctx[i]*Wv[(size_t)i*DIM + t];
        sp[pc][tc] = a;
        __syncthreads();
        if (tid < 64)
            g_bvp[b*64+tid] = sp[0][tid]+sp[1][tid]+sp[2][tid]+sp[3][tid] + bv[b*64+tid];
    } else if (b < 16){
        const int t = (b-8)*64 + tc;
        float a = 0.f;
        #pragma unroll 4
        for (int i = pc*128; i < pc*128+128; i++) a += g_colsum[i]*Wctx[(size_t)i*DIM + t];
        sp[pc][tc] = a;
        __syncthreads();
        if (tid < 64)
            g_h[0][(b-8)*64+tid] = (sp[0][tid]+sp[1][tid]+sp[2][tid]+sp[3][tid])*(1.0f/(float)NFR)
                                   + bctx[(b-8)*64+tid];
    } else {
        const int h = b - 16;
        #pragma unroll
        for (int rr = 0; rr < 2; rr++){
            int i = rr*256 + tid;
            float s = 0.f;
            #pragma unroll 8
            for (int d = 0; d < 64; d++)
                s += g_WckT[(size_t)(h*64+d)*DIM + i]*bq[h*64+d];
            g_cvec[h*DIM + i] = s;
        }
    }
}

// bih2 (b<24): bih2 = b_ih + Wih2_ctx@bvp + W_ih_ctx@bo ; b=24: start copy
__global__ void p4y(const float* __restrict__ W_ih, const float* __restrict__ b_ih,
                    const float* __restrict__ bo,   const float* __restrict__ start){
    const int b = blockIdx.x, tid = threadIdx.x;
    if (b == 24){
        if (tid < ATTR) g_x[tid] = start[tid];
        return;
    }
    __shared__ float sbvp[DIM];
    __shared__ float sbo[DIM];
    #pragma unroll
    for (int rr = 0; rr < 2; rr++){
        int t = rr*256 + tid;
        sbvp[t] = g_bvp[t];
        sbo[t]  = bo[t];
    }
    __syncthreads();
    const int w = tid >> 5, lane = tid & 31;
    const int r0 = b*64;
    for (int rr = w; rr < 64; rr += 8){
        int r = r0 + rr;
        const float4* W2 = (const float4*)(g_Wih2 + (size_t)r*XDIM + 256);
        const float4* WI = (const float4*)(W_ih + (size_t)r*XDIM + 256);
        float a = 0.f;
        #pragma unroll
        for (int k = 0; k < 4; k++){
            float4 w2 = W2[lane+32*k];
            float4 wi = WI[lane+32*k];
            int kb = (lane+32*k)*4;
            a += w2.x*sbvp[kb+0] + w2.y*sbvp[kb+1] + w2.z*sbvp[kb+2] + w2.w*sbvp[kb+3];
            a += wi.x*sbo[kb+0]  + wi.y*sbo[kb+1]  + wi.z*sbo[kb+2]  + wi.w*sbo[kb+3];
        }
        a = wred(a);
        if (lane == 0) g_bih2[r] = a + b_ih[r];
    }
}

// ----------------------------- per-step ----------------------------------
// pre-loop: u = A@h0 + cvec ; block 0 zeroes vraw. grid 128 x 256.
__global__ void s1_u(){
    const int tid = threadIdx.x, w = tid >> 5, lane = tid & 31;
    if (blockIdx.x == 0){ g_x[256+tid] = 0.f; g_x[512+tid] = 0.f; }
    const float4* H4 = (const float4*)g_h[0];
    float4 hv[4];
    #pragma unroll
    for (int k = 0; k < 4; k++) hv[k] = H4[lane + 32*k];
    const int gw = blockIdx.x*8 + w;
    #pragma unroll
    for (int rr = 0; rr < 4; rr++){
        int r = gw + rr*1024;
        const float4* A4 = (const float4*)(g_A + (size_t)r*DIM);
        float a = 0.f;
        #pragma unroll
        for (int k = 0; k < 4; k++){
            float4 av = A4[lane + 32*k];
            a += av.x*hv[k].x + av.y*hv[k].y + av.z*hv[k].z + av.w*hv[k].w;
        }
        a = wred(a);
        if (lane == 0) g_u[r] = a + g_cvec[r];
    }
}

// Fused single-pass flash attention. grid 148 x 512. warp = head, 2 streams/block.
__global__ void __launch_bounds__(512,1) sA(){
    const int tid = threadIdx.x, w = tid >> 5, lane = tid & 31;
    const int head = w & 7, grp = w >> 3;
    const int stream = blockIdx.x*2 + grp;          // 0..295

    ull u[8];
    {
        const float4* U4 = (const float4*)(g_u + head*DIM);
        #pragma unroll
        for (int jj = 0; jj < 2; jj++){
            float4 va = U4[2*lane + 64*jj];
            float4 vb = U4[2*lane + 64*jj + 1];
            u[4*jj+0] = fpack(va.x, va.y);
            u[4*jj+1] = fpack(va.z, va.w);
            u[4*jj+2] = fpack(vb.x, vb.y);
            u[4*jj+3] = fpack(vb.z, vb.w);
        }
    }
    ull acc[8];
    #pragma unroll
    for (int j = 0; j < 8; j++) acc[j] = 0ull;
    float m = -3.0e38f, s = 0.f;

    const uint4* Fq = (const uint4*)g_Fh;
    int n = stream;
    uint4 ra = Fq[(size_t)n*64 + lane];
    uint4 rb = Fq[(size_t)n*64 + lane + 32];
    for (;;){
        int nn = n + NSTREAM;
        bool more = nn < NFR;
        uint4 na, nb;
        if (more){
            size_t rq = (size_t)nn*64;
            na = Fq[rq + lane]; nb = Fq[rq + lane + 32];
        }
        ull f0 = bfp(ra.x), f1 = bfp(ra.y), f2 = bfp(ra.z), f3 = bfp(ra.w);
        ull f4 = bfp(rb.x), f5 = bfp(rb.y), f6 = bfp(rb.z), f7 = bfp(rb.w);
        ull l0 = 0ull, l1 = 0ull;
        FMA2(l0, f0, u[0]); FMA2(l1, f1, u[1]);
        FMA2(l0, f2, u[2]); FMA2(l1, f3, u[3]);
        FMA2(l0, f4, u[4]); FMA2(l1, f5, u[5]);
        FMA2(l0, f6, u[6]); FMA2(l1, f7, u[7]);
        float2 pa = funp(l0), pb = funp(l1);
        float l = (pa.x + pb.x) + (pa.y + pb.y);
        l = wred(l);
        if (l > m){                                // warp-uniform
            float sc = __expf(m - l);
            s *= sc;
            ull scp = fpack(sc, sc);
            #pragma unroll
            for (int j = 0; j < 8; j++) MUL2(acc[j], acc[j], scp);
            m = l;
        }
        float e = __expf(l - m);
        s += e;
        ull ee = fpack(e, e);
        FMA2(acc[0], ee, f0); FMA2(acc[1], ee, f1);
        FMA2(acc[2], ee, f2); FMA2(acc[3], ee, f3);
        FMA2(acc[4], ee, f4); FMA2(acc[5], ee, f5);
        FMA2(acc[6], ee, f6); FMA2(acc[7], ee, f7);
        if (!more) break;
        n = nn; ra = na; rb = nb;
    }

    // pair-combine (warp w with w+8, same head); transposed partial store
    __shared__ float sm_[16], ss_[16];
    __shared__ __align__(16) float sacc[16*512];
    if (lane == 0){ sm_[w] = m; ss_[w] = s; }
    float* base = sacc + w*512;
    #pragma unroll
    for (int jj = 0; jj < 2; jj++){
        float2 v0 = funp(acc[4*jj+0]), v1 = funp(acc[4*jj+1]);
        float2 v2 = funp(acc[4*jj+2]), v3 = funp(acc[4*jj+3]);
        *(float4*)&base[8*lane + 256*jj]     = make_float4(v0.x, v0.y, v1.x, v1.y);
        *(float4*)&base[8*lane + 256*jj + 4] = make_float4(v2.x, v2.y, v3.x, v3.y);
    }
    __syncthreads();
    if (w < 8){
        float m1 = sm_[w], m2 = sm_[w+8];
        float M = fmaxf(m1, m2);
        float c1 = __expf(m1 - M), c2 = __expf(m2 - M);
        const float* b1 = sacc + w*512;
        const float* b2 = sacc + (w+8)*512;
        const int bi = blockIdx.x;
        #pragma unroll
        for (int t = lane; t < 512; t += 32){
            float v = b1[t]*c1 + b2[t]*c2;
            g_wpartT[(size_t)(w*512 + t)*WPAD + bi] = v;
        }
        if (lane == 0){
            g_spart[bi*8 + w] = ss_[w]*c1 + ss_[w+8]*c2;
            g_mpart[bi*8 + w] = M;
        }
    }
}

// combine partials (coalesced, exact m-realign) -> c ; vraw += c@Wcv. grid 16 x 256.
__global__ void s3c(){
    __shared__ float sef[GRIDA];
    __shared__ float sMS[2];
    __shared__ float scv[256];
    __shared__ float sv[4][64];
    const int tid = threadIdx.x, bi = blockIdx.x;
    const int hb = bi >> 1;
    // per-head max/sum over partials
    __shared__ float smv[GRIDA];
    if (tid < GRIDA) smv[tid] = g_mpart[tid*8 + hb];
    __syncthreads();
    if (tid < 32){
        float M = -3.0e38f;
        for (int b = tid; b < GRIDA; b += 32) M = fmaxf(M, smv[b]);
        #pragma unroll
        for (int o = 16; o; o >>= 1) M = fmaxf(M, __shfl_xor_sync(0xffffffffu, M, o));
        if (tid == 0) sMS[0] = M;
    }
    __syncthreads();
    if (tid < GRIDA) sef[tid] = __expf(smv[tid] - sMS[0]);
    __syncthreads();
    if (tid < 32){
        float S = 0.f;
        for (int b = tid; b < GRIDA; b += 32) S += g_spart[b*8 + hb]*sef[b];
        S = wred(S);
        if (tid == 0) sMS[1] = S;
    }
    __syncthreads();
    const int idx = bi*256 + tid;                 // = hb*512 + c
    {
        const float4* P4 = (const float4*)(g_wpartT + (size_t)idx*WPAD);
        float a = 0.f;
        #pragma unroll 4
        for (int b4 = 0; b4 < GRIDA/4; b4++){
            float4 pv = P4[b4];
            a += pv.x*sef[b4*4+0] + pv.y*sef[b4*4+1]
               + pv.z*sef[b4*4+2] + pv.w*sef[b4*4+3];
        }
        scv[tid] = a / sMS[1];
    }
    __syncthreads();
    const int d = tid & 63, isub = tid >> 6;
    const int i0 = (bi & 1)*256;
    float pv = 0.f;
    #pragma unroll 8
    for (int ii = 0; ii < 64; ii++){
        int i = i0 + isub*64 + ii;
        pv += scv[isub*64+ii]*g_Wcv[(size_t)i*DIM + hb*64 + d];
    }
    sv[isub][d] = pv;
    __syncthreads();
    if (tid < 64)
        atomicAdd(&g_x[256 + hb*64 + tid],
                  sv[0][tid]+sv[1][tid]+sv[2][tid]+sv[3][tid]);
}

// GRU matvecs
__global__ void s5_gru(const float* __restrict__ W_hh, int p){
    const int warp = threadIdx.x >> 5, lane = threadIdx.x & 31;
    const int gw = blockIdx.x*8 + warp, nw = gridDim.x*8;
    for (int r = gw; r < 3072; r += nw){
        float a = 0.f;
        if (r < 1536){
            const float4* W = (const float4*)(g_Wih2 + (size_t)r*XDIM);
            const float4* X = (const float4*)g_x;
            #pragma unroll
            for (int k = 0; k < 6; k++){
                float4 w = W[lane + 32*k], x = X[lane + 32*k];
                a += w.x*x.x + w.y*x.y + w.z*x.z + w.w*x.w;
            }
            a = wred(a);
            if (lane == 0) g_ihh[r] = a + g_bih2[r];
        } else {
            int rr = r - 1536;
            const float4* W = (const float4*)(W_hh + (size_t)rr*DIM);
            const float4* H = (const float4*)g_h[p];
            #pragma unroll
            for (int k = 0; k < 4; k++){
                float4 w = W[lane + 32*k], h = H[lane + 32*k];
                a += w.x*h.x + w.y*h.y + w.z*h.z + w.w*h.w;
            }
            a = wred(a);
            if (lane == 0) g_ihh[r] = a;
        }
    }
}

// gates + heads + output + u for NEXT step + vraw zero. grid 16 x 256.
__global__ void s6u(int p, int step, float* __restrict__ out,
                    const float* __restrict__ b_hn,
                    const float* __restrict__ W_attr, const float* __restrict__ b_attr,
                    const float* __restrict__ W_conf, const float* __restrict__ b_conf){
    __shared__ __align__(16) float hn[DIM];
    const int tid = threadIdx.x;
    for (int j = tid; j < DIM; j += 256){
        float ihr = g_ihh[j],      ihz = g_ihh[512+j],  ihn = g_ihh[1024+j];
        float hhr = g_ihh[1536+j], hhz = g_ihh[2048+j], hhn = g_ihh[2560+j];
        float r = 1.0f/(1.0f + expf(-(ihr + hhr)));
        float z = 1.0f/(1.0f + expf(-(ihz + hhz)));
        float nn = tanhf(ihn + r*(hhn + b_hn[j]));
        float h = (1.0f - z)*nn + z*g_h[p][j];
        hn[j] = h;
        if (blockIdx.x == 0) g_h[1-p][j] = h;
    }
    __syncthreads();
    const int warp = tid >> 5, lane = tid & 31;
    const int gw = blockIdx.x*8 + warp;
    const float4* H4 = (const float4*)hn;
    float4 hv[4];
    #pragma unroll
    for (int k = 0; k < 4; k++) hv[k] = H4[lane + 32*k];
    #pragma unroll
    for (int rr = 0; rr < 2; rr++){
        int row = gw*2 + rr;
        const float4* W = (const float4*)(W_attr + (size_t)row*DIM);
        float a = 0.f;
        #pragma unroll
        for (int k = 0; k < 4; k++){
            float4 w = W[lane + 32*k];
            a += w.x*hv[k].x + w.y*hv[k].y + w.z*hv[k].z + w.w*hv[k].w;
        }
        a = wred(a);
        if (lane == 0){
            float v = a + b_attr[row];
            out[step*ATTR + row] = v;
            g_x[row] = v;
        }
    }
    if (gw == 0){
        const float4* W = (const float4*)W_conf;
        float a = 0.f;
        #pragma unroll
        for (int k = 0; k < 4; k++){
            float4 w = W[lane + 32*k];
            a += w.x*hv[k].x + w.y*hv[k].y + w.z*hv[k].z + w.w*hv[k].w;
        }
        a = wred(a);
        if (lane == 0)
            out[KSTEPS*ATTR + step] = 1.0f/(1.0f + expf(-(a + b_conf[0])));
    }
    // u' = A @ h_new + cvec for the next step; zero vraw
    if (blockIdx.x == 0){ g_x[256+tid] = 0.f; g_x[512+tid] = 0.f; }
    const int rbase = blockIdx.x*256 + warp*32;
    for (int rloc = 0; rloc < 32; rloc++){
        int r = rbase + rloc;
        const float4* A4 = (const float4*)(g_A + (size_t)r*DIM);
        float a = 0.f;
        #pragma unroll
        for (int k = 0; k < 4; k++){
            float4 av = A4[lane + 32*k];
            a += av.x*hv[k].x + av.y*hv[k].y + av.z*hv[k].z + av.w*hv[k].w;
        }
        a = wred(a);
        if (lane == 0) g_u[r] = a + g_cvec[r];
    }
}

// ------------------------------- launch -----------------------------------
extern "C" void kernel_launch(void* const* d_in, const int* in_sizes, int n_in,
                              void* d_out, int out_size){
    const float* F      = (const float*)d_in[0];
    const float* Wctx   = (const float*)d_in[1];
    const float* bctx   = (const float*)d_in[2];
    const float* Wq     = (const float*)d_in[3];
    const float* bq     = (const float*)d_in[4];
    const float* Wk     = (const float*)d_in[5];
    // d_in[6] = bk : softmax-invariant, unused
    const float* Wv     = (const float*)d_in[7];
    const float* bv     = (const float*)d_in[8];
    const float* Wo     = (const float*)d_in[9];
    const float* bo     = (const float*)d_in[10];
    const float* W_ih   = (const float*)d_in[11];
    const float* W_hh   = (const float*)d_in[12];
    const float* b_ih   = (const float*)d_in[13];
    const float* b_hn   = (const float*)d_in[14];
    const float* start  = (const float*)d_in[15];
    const float* W_attr = (const float*)d_in[16];
    const float* b_attr = (const float*)d_in[17];
    const float* W_conf = (const float*)d_in[18];
    const float* b_conf = (const float*)d_in[19];
    float* out = (float*)d_out;

    p1c<<<1024, 256>>>((const float4*)F);
    p2 <<<dim3(16,16,3), dim3(32,8)>>>(Wctx, Wk, Wv);
    pAB<<<dim3(16,24,9), 256>>>(Wq, W_ih, Wo);
    p4v<<<24, 256>>>(Wctx, bctx, bq, Wv, bv);
    p4y<<<25, 256>>>(W_ih, b_ih, bo, start);
    s1_u<<<128, 256>>>();

    for (int step = 0; step < KSTEPS; step++){
        int p = step & 1;
        sA  <<<GRIDA, 512>>>();
        s3c <<<16, 256>>>();
        s5_gru<<<96, 256>>>(W_hh, p);
        s6u <<<16, 256>>>(p, step, out, b_hn, W_attr, b_attr, W_conf, b_conf);
    }
}

// round 8
// speedup vs baseline: 1.2607x; 1.2607x over previous
#include <cuda_runtime.h>
#include <cuda_bf16.h>
#include <math.h>

#define NFR    65536
#define DIM    512
#define HEADS  8
#define ATTR   256
#define XDIM   768
#define KSTEPS 16
#define SCALE  0.125f
#define NSTREAM 296
#define GRIDA  148
#define ROWSTRIDE 592        // 2*NSTREAM (2 rows per iteration)
#define ESHIFT 10.0f         // constant logit shift (exactly softmax-invariant)

// ------------------------- static device scratch -------------------------
__device__ __align__(16) __nv_bfloat16 g_Fh[NFR*DIM];    // bf16 frames (64MB)
__device__ __align__(16) float g_WckT[DIM*DIM];          // scale*(W_ctx@Wk)^T [o][i]
__device__ __align__(16) float g_Wcv [DIM*DIM];          // W_ctx@Wv [i][o]
__device__ __align__(16) float g_A[HEADS*DIM*DIM];       // A_h = WckT_h @ Wq_h^T (8MB)
__device__ __align__(16) float g_Wih2[1536*XDIM];        // [W_ih[:,:256] | W_ih[:,256:]@Wo^T]
__device__ __align__(16) float g_bih2[1536];
__device__ __align__(16) float g_cvec[HEADS*DIM];
__device__ __align__(16) float g_cspart[1024*DIM];       // per-block colsum partials
__device__ __align__(16) float g_colsum[DIM];
__device__ __align__(16) float g_bvp[DIM];
__device__ __align__(16) float g_h[2][DIM];
__device__ __align__(16) float g_u[HEADS*DIM];           // [h][i]
__device__ __align__(16) float g_x[XDIM];                // [a_prev(256); vraw(512)]
__device__ __align__(16) float g_ihh[3072];
__device__ __align__(16) float g_wpart[GRIDA*4096];      // per-block weighted sums [b][h*512+c]
__device__ float g_spart[GRIDA*HEADS];

__device__ __forceinline__ float wred(float a){
    #pragma unroll
    for (int o = 16; o; o >>= 1) a += __shfl_xor_sync(0xffffffffu, a, o);
    return a;
}
// ---- packed fp32 (f32x2) helpers ----
typedef unsigned long long ull;
#define FMA2(d,a,b) asm("fma.rn.f32x2 %0, %1, %2, %0;" : "+l"(d) : "l"(a), "l"(b))
__device__ __forceinline__ ull fpack(float a, float b){
    ull r; asm("mov.b64 %0, {%1, %2};" : "=l"(r) : "f"(a), "f"(b)); return r;
}
__device__ __forceinline__ ull bfp(unsigned w){
    unsigned lo = w << 16, hi = w & 0xffff0000u;
    ull r; asm("mov.b64 %0, {%1, %2};" : "=l"(r) : "r"(lo), "r"(hi)); return r;
}
__device__ __forceinline__ float2 funp(ull v){
    float x, y; asm("mov.b64 {%0, %1}, %2;" : "=f"(x), "=f"(y) : "l"(v));
    return make_float2(x, y);
}

// ------------------------------ setup ------------------------------------
// F -> bf16 + per-block colsum partials. grid 1024 x 256.
__global__ void p1c(const float4* __restrict__ F4){
    const int tid = threadIdx.x, col = tid & 127, rh = tid >> 7;
    const int r0 = blockIdx.x*64;
    float4 acc = make_float4(0.f,0.f,0.f,0.f);
    uint2* out = (uint2*)g_Fh;
    for (int i = 0; i < 32; i++){
        size_t row = r0 + i*2 + rh;
        float4 f = F4[row*128 + col];
        acc.x += f.x; acc.y += f.y; acc.z += f.z; acc.w += f.w;
        uint2 pk;
        pk.x = ((unsigned)__bfloat16_as_ushort(__float2bfloat16_rn(f.y)) << 16)
             |  (unsigned)__bfloat16_as_ushort(__float2bfloat16_rn(f.x));
        pk.y = ((unsigned)__bfloat16_as_ushort(__float2bfloat16_rn(f.w)) << 16)
             |  (unsigned)__bfloat16_as_ushort(__float2bfloat16_rn(f.z));
        out[row*128 + col] = pk;
    }
    __shared__ float cs[512];
    if (rh == 0){
        cs[col*4+0]=acc.x; cs[col*4+1]=acc.y; cs[col*4+2]=acc.z; cs[col*4+3]=acc.w;
    }
    __syncthreads();
    if (rh == 1){
        size_t b = (size_t)blockIdx.x*512 + col*4;
        g_cspart[b+0] = cs[col*4+0]+acc.x;
        g_cspart[b+1] = cs[col*4+1]+acc.y;
        g_cspart[b+2] = cs[col*4+2]+acc.z;
        g_cspart[b+3] = cs[col*4+3]+acc.w;
    }
}

// z=0: WckT = scale*(W_ctx@Wk)^T ; z=1: Wcv = W_ctx@Wv ; z=2: colsum reduce
__global__ void p2(const float* __restrict__ Wctx,
                   const float* __restrict__ Wk,
                   const float* __restrict__ Wv){
    if (blockIdx.z == 2){
        if (blockIdx.y != 0) return;
        const int tid = threadIdx.y*32 + threadIdx.x;
        const int col = blockIdx.x*32 + (tid & 31), seg = tid >> 5;
        float a = 0.f;
        #pragma unroll 8
        for (int p = seg*128; p < seg*128+128; p++) a += g_cspart[(size_t)p*512 + col];
        __shared__ float sr[8][33];
        sr[seg][tid & 31] = a;
        __syncthreads();
        if (tid < 32){
            float s2 = 0.f;
            #pragma unroll
            for (int q = 0; q < 8; q++) s2 += sr[q][tid];
            g_colsum[blockIdx.x*32 + tid] = s2;
        }
        return;
    }
    __shared__ float sA[32][33];
    __shared__ float sB[32][33];
    int tx = threadIdx.x, ty = threadIdx.y;
    const float* B = blockIdx.z ? Wv : Wk;
    int i0 = blockIdx.y*32, j0 = blockIdx.x*32;
    float acc[4] = {0.f,0.f,0.f,0.f};
    for (int m0 = 0; m0 < DIM; m0 += 32){
        #pragma unroll
        for (int k = 0; k < 4; k++){
            sA[ty+8*k][tx] = Wctx[(size_t)(i0+ty+8*k)*DIM + m0+tx];
            sB[ty+8*k][tx] = B[(size_t)(m0+ty+8*k)*DIM + j0+tx];
        }
        __syncthreads();
        #pragma unroll
        for (int mm = 0; mm < 32; mm++){
            float b = sB[mm][tx];
            #pragma unroll
            for (int k = 0; k < 4; k++) acc[k] += sA[ty+8*k][mm]*b;
        }
        __syncthreads();
    }
    if (blockIdx.z){
        #pragma unroll
        for (int k = 0; k < 4; k++)
            g_Wcv[(size_t)(i0+ty+8*k)*DIM + j0+tx] = acc[k];
    } else {
        __syncthreads();
        #pragma unroll
        for (int k = 0; k < 4; k++) sA[tx][ty+8*k] = acc[k];
        __syncthreads();
        #pragma unroll
        for (int k = 0; k < 4; k++)
            g_WckT[(size_t)(j0+ty+8*k)*DIM + i0+tx] = SCALE*sA[ty+8*k][tx];
    }
}

// z<8: A_h[i][j] = sum_d WckT[h*64+d][i]*Wq[j][h*64+d] ; z=8: Wih2 build
__global__ __launch_bounds__(256) void pAB(const float* __restrict__ Wq,
                                           const float* __restrict__ W_ih,
                                           const float* __restrict__ Wo){
    const int tid = threadIdx.x;
    const int z = blockIdx.z;
    if (z < 8){
        if (blockIdx.y >= 16) return;
        __shared__ float sA_[32][65];
        __shared__ float sB_[32][65];
        const int h = z, i0 = blockIdx.y*32, j0 = blockIdx.x*32;
        for (int e = tid; e < 2048; e += 256){
            int r = e & 31, d = e >> 5;
            sA_[r][d] = g_WckT[(size_t)(h*64+d)*DIM + i0 + r];
        }
        for (int e = tid; e < 2048; e += 256){
            int rj = e >> 6, d = e & 63;
            sB_[rj][d] = Wq[(size_t)(j0+rj)*DIM + h*64 + d];
        }
        __syncthreads();
        const int tx = tid & 31, ty = tid >> 5;
        float acc[4] = {0.f,0.f,0.f,0.f};
        #pragma unroll 8
        for (int d = 0; d < 64; d++){
            float bb = sB_[tx][d];
            #pragma unroll
            for (int k = 0; k < 4; k++) acc[k] += sA_[ty+8*k][d]*bb;
        }
        #pragma unroll
        for (int k = 0; k < 4; k++)
            g_A[(size_t)(h*DIM + i0+ty+8*k)*DIM + j0+tx] = acc[k];
    } else {
        const int i0 = blockIdx.y*64;
        if (blockIdx.x < 8){
            __shared__ float sA[64][33];
            __shared__ float sB[64][33];
            const int j0 = blockIdx.x*64;
            const int tx = tid & 15, ty = tid >> 4;
            float acc[4][4];
            #pragma unroll
            for (int a = 0; a < 4; a++)
                #pragma unroll
                for (int b = 0; b < 4; b++) acc[a][b] = 0.f;
            for (int m0 = 0; m0 < DIM; m0 += 32){
                #pragma unroll
                for (int q = 0; q < 2; q++){
                    int e = tid + q*256, r = e >> 3, c = e & 7;
                    float4 va = *(const float4*)(W_ih + (size_t)(i0+r)*XDIM + 256 + m0 + c*4);
                    sA[r][c*4+0]=va.x; sA[r][c*4+1]=va.y; sA[r][c*4+2]=va.z; sA[r][c*4+3]=va.w;
                    float4 vb = *(const float4*)(Wo + (size_t)(j0+r)*DIM + m0 + c*4);
                    sB[r][c*4+0]=vb.x; sB[r][c*4+1]=vb.y; sB[r][c*4+2]=vb.z; sB[r][c*4+3]=vb.w;
                }
                __syncthreads();
                #pragma unroll
                for (int m = 0; m < 32; m++){
                    float a4[4], b4[4];
                    #pragma unroll
                    for (int k = 0; k < 4; k++){ a4[k] = sA[ty*4+k][m]; b4[k] = sB[tx*4+k][m]; }
                    #pragma unroll
                    for (int a = 0; a < 4; a++)
                        #pragma unroll
                        for (int b = 0; b < 4; b++) acc[a][b] += a4[a]*b4[b];
                }
                __syncthreads();
            }
            #pragma unroll
            for (int a = 0; a < 4; a++){
                float4 v = make_float4(acc[a][0], acc[a][1], acc[a][2], acc[a][3]);
                *(float4*)(g_Wih2 + (size_t)(i0+ty*4+a)*XDIM + 256 + j0 + tx*4) = v;
            }
        } else if (blockIdx.x < 12){
            const int c0 = (blockIdx.x-8)*64;
            for (int e = tid; e < 64*16; e += 256){
                int r = e >> 4, c = e & 15;
                *(float4*)(g_Wih2 + (size_t)(i0+r)*XDIM + c0 + c*4) =
                    *(const float4*)(W_ih + (size_t)(i0+r)*XDIM + c0 + c*4);
            }
        }
    }
}

// parallel vectors: bvp (b<8), h0 (b<16), cvec (b<24)
__global__ void p4v(const float* __restrict__ Wctx, const float* __restrict__ bctx,
                    const float* __restrict__ bq,   const float* __restrict__ Wv,
                    const float* __restrict__ bv){
    const int b = blockIdx.x, tid = threadIdx.x;
    __shared__ float sp[4][64];
    const int tc = tid & 63, pc = tid >> 6;
    if (b < 8){
        const int t = b*64 + tc;
        float a = 0.f;
        #pragma unroll 4
        for (int i = pc*128; i < pc*128+128; i++) a += bctx[i]*Wv[(size_t)i*DIM + t];
        sp[pc][tc] = a;
        __syncthreads();
        if (tid < 64)
            g_bvp[b*64+tid] = sp[0][tid]+sp[1][tid]+sp[2][tid]+sp[3][tid] + bv[b*64+tid];
    } else if (b < 16){
        const int t = (b-8)*64 + tc;
        float a = 0.f;
        #pragma unroll 4
        for (int i = pc*128; i < pc*128+128; i++) a += g_colsum[i]*Wctx[(size_t)i*DIM + t];
        sp[pc][tc] = a;
        __syncthreads();
        if (tid < 64)
            g_h[0][(b-8)*64+tid] = (sp[0][tid]+sp[1][tid]+sp[2][tid]+sp[3][tid])*(1.0f/(float)NFR)
                                   + bctx[(b-8)*64+tid];
    } else {
        const int h = b - 16;
        #pragma unroll
        for (int rr = 0; rr < 2; rr++){
            int i = rr*256 + tid;
            float s = 0.f;
            #pragma unroll 8
            for (int d = 0; d < 64; d++)
                s += g_WckT[(size_t)(h*64+d)*DIM + i]*bq[h*64+d];
            g_cvec[h*DIM + i] = s;
        }
    }
}

// shared u-matvec body: u = A@h + cvec for 32 rows per (block,warp); 128 virtual blocks
__device__ __forceinline__ void u_body(int bx, int tid, const float* __restrict__ hsrc){
    const int w = tid >> 5, lane = tid & 31;
    if (bx == 0){ g_x[256+tid] = 0.f; g_x[512+tid] = 0.f; }
    const float4* H4 = (const float4*)hsrc;
    float4 hv[4];
    #pragma unroll
    for (int k = 0; k < 4; k++) hv[k] = H4[lane + 32*k];
    const int gw = bx*8 + w;
    #pragma unroll
    for (int rr = 0; rr < 4; rr++){
        int r = gw + rr*1024;
        const float4* A4 = (const float4*)(g_A + (size_t)r*DIM);
        float a = 0.f;
        #pragma unroll
        for (int k = 0; k < 4; k++){
            float4 av = A4[lane + 32*k];
            a += av.x*hv[k].x + av.y*hv[k].y + av.z*hv[k].z + av.w*hv[k].w;
        }
        a = wred(a);
        if (lane == 0) g_u[r] = a + g_cvec[r];
    }
}

// b<24: bih2 ; b=24: start copy ; b>=25: pre-loop u = A@h0 + cvec. grid 153.
__global__ void p4y(const float* __restrict__ W_ih, const float* __restrict__ b_ih,
                    const float* __restrict__ bo,   const float* __restrict__ start){
    const int b = blockIdx.x, tid = threadIdx.x;
    if (b >= 25){ u_body(b-25, tid, g_h[0]); return; }
    if (b == 24){
        if (tid < ATTR) g_x[tid] = start[tid];
        return;
    }
    __shared__ float sbvp[DIM];
    __shared__ float sbo[DIM];
    #pragma unroll
    for (int rr = 0; rr < 2; rr++){
        int t = rr*256 + tid;
        sbvp[t] = g_bvp[t];
        sbo[t]  = bo[t];
    }
    __syncthreads();
    const int w = tid >> 5, lane = tid & 31;
    const int r0 = b*64;
    for (int rr = w; rr < 64; rr += 8){
        int r = r0 + rr;
        const float4* W2 = (const float4*)(g_Wih2 + (size_t)r*XDIM + 256);
        const float4* WI = (const float4*)(W_ih + (size_t)r*XDIM + 256);
        float a = 0.f;
        #pragma unroll
        for (int k = 0; k < 4; k++){
            float4 w2 = W2[lane+32*k];
            float4 wi = WI[lane+32*k];
            int kb = (lane+32*k)*4;
            a += w2.x*sbvp[kb+0] + w2.y*sbvp[kb+1] + w2.z*sbvp[kb+2] + w2.w*sbvp[kb+3];
            a += wi.x*sbo[kb+0]  + wi.y*sbo[kb+1]  + wi.z*sbo[kb+2]  + wi.w*sbo[kb+3];
        }
        a = wred(a);
        if (lane == 0) g_bih2[r] = a + b_ih[r];
    }
}

// ----------------------------- per-step ----------------------------------
// per-step u for next iteration. grid 128 x 256.
__global__ void s1_u(int p){
    u_body(blockIdx.x, threadIdx.x, g_h[p]);
}

// Fused one-pass attention, no-max softmax (constant shift, exactly invariant).
// grid 148 x 512. warp = head, 2 streams/block, 2 rows per iteration.
__global__ void __launch_bounds__(512,1) sA(){
    const int tid = threadIdx.x, w = tid >> 5, lane = tid & 31;
    const int head = w & 7, grp = w >> 3;
    const int stream = blockIdx.x*2 + grp;          // 0..295

    ull u[8];
    {
        const float4* U4 = (const float4*)(g_u + head*DIM);
        #pragma unroll
        for (int jj = 0; jj < 2; jj++){
            float4 va = U4[2*lane + 64*jj];
            float4 vb = U4[2*lane + 64*jj + 1];
            u[4*jj+0] = fpack(va.x, va.y);
            u[4*jj+1] = fpack(va.z, va.w);
            u[4*jj+2] = fpack(vb.x, vb.y);
            u[4*jj+3] = fpack(vb.z, vb.w);
        }
    }
    ull acc[8];
    #pragma unroll
    for (int j = 0; j < 8; j++) acc[j] = 0ull;
    float s = 0.f;

    const uint4* Fq = (const uint4*)g_Fh;
    for (int n = stream*2; n < NFR; n += ROWSTRIDE){
        const size_t q0 = (size_t)n*64, q1 = q0 + 64;
        uint4 ra = Fq[q0 + lane], rb = Fq[q0 + lane + 32];
        uint4 rc = Fq[q1 + lane], rd = Fq[q1 + lane + 32];
        ull f0 = bfp(ra.x), f1 = bfp(ra.y), f2 = bfp(ra.z), f3 = bfp(ra.w);
        ull f4 = bfp(rb.x), f5 = bfp(rb.y), f6 = bfp(rb.z), f7 = bfp(rb.w);
        ull g0 = bfp(rc.x), g1 = bfp(rc.y), g2 = bfp(rc.z), g3 = bfp(rc.w);
        ull g4 = bfp(rd.x), g5 = bfp(rd.y), g6 = bfp(rd.z), g7 = bfp(rd.w);
        ull l0 = 0ull, l1 = 0ull, l2 = 0ull, l3 = 0ull;
        FMA2(l0, f0, u[0]); FMA2(l1, f1, u[1]); FMA2(l2, g0, u[0]); FMA2(l3, g1, u[1]);
        FMA2(l0, f2, u[2]); FMA2(l1, f3, u[3]); FMA2(l2, g2, u[2]); FMA2(l3, g3, u[3]);
        FMA2(l0, f4, u[4]); FMA2(l1, f5, u[5]); FMA2(l2, g4, u[4]); FMA2(l3, g5, u[5]);
        FMA2(l0, f6, u[6]); FMA2(l1, f7, u[7]); FMA2(l2, g6, u[6]); FMA2(l3, g7, u[7]);
        float2 pa = funp(l0), pb = funp(l1), pc = funp(l2), pd = funp(l3);
        float la = (pa.x + pb.x) + (pa.y + pb.y);
        float lb = (pc.x + pd.x) + (pc.y + pd.y);
        #pragma unroll
        for (int o = 16; o; o >>= 1){       // two interleaved reduction chains
            la += __shfl_xor_sync(0xffffffffu, la, o);
            lb += __shfl_xor_sync(0xffffffffu, lb, o);
        }
        float e1 = __expf(la - ESHIFT);
        float e2 = __expf(lb - ESHIFT);
        s += e1 + e2;
        ull ee1 = fpack(e1, e1), ee2 = fpack(e2, e2);
        FMA2(acc[0], ee1, f0); FMA2(acc[1], ee1, f1);
        FMA2(acc[2], ee1, f2); FMA2(acc[3], ee1, f3);
        FMA2(acc[4], ee1, f4); FMA2(acc[5], ee1, f5);
        FMA2(acc[6], ee1, f6); FMA2(acc[7], ee1, f7);
        FMA2(acc[0], ee2, g0); FMA2(acc[1], ee2, g1);
        FMA2(acc[2], ee2, g2); FMA2(acc[3], ee2, g3);
        FMA2(acc[4], ee2, g4); FMA2(acc[5], ee2, g5);
        FMA2(acc[6], ee2, g6); FMA2(acc[7], ee2, g7);
    }

    // pair-combine (warp w with w+8, same head): plain sums, coalesced store
    __shared__ float ss_[16];
    __shared__ __align__(16) float sacc[16*512];
    if (lane == 0) ss_[w] = s;
    float* base = sacc + w*512;
    #pragma unroll
    for (int jj = 0; jj < 2; jj++){
        float2 v0 = funp(acc[4*jj+0]), v1 = funp(acc[4*jj+1]);
        float2 v2 = funp(acc[4*jj+2]), v3 = funp(acc[4*jj+3]);
        *(float4*)&base[8*lane + 256*jj]     = make_float4(v0.x, v0.y, v1.x, v1.y);
        *(float4*)&base[8*lane + 256*jj + 4] = make_float4(v2.x, v2.y, v3.x, v3.y);
    }
    __syncthreads();
    if (w < 8){
        const float* b1 = sacc + w*512;
        const float* b2 = sacc + (w+8)*512;
        float* op = g_wpart + (size_t)blockIdx.x*4096 + w*512;
        #pragma unroll
        for (int t = lane*4; t < 512; t += 128){
            float4 x1 = *(const float4*)&b1[t];
            float4 x2 = *(const float4*)&b2[t];
            *(float4*)&op[t] = make_float4(x1.x+x2.x, x1.y+x2.y, x1.z+x2.z, x1.w+x2.w);
        }
        if (lane == 0) g_spart[blockIdx.x*8 + w] = ss_[w] + ss_[w+8];
    }
}

// combine partials (plain sum, coalesced) -> c ; vraw += c@Wcv. grid 16 x 256.
__global__ void s3c(){
    __shared__ float sS;
    __shared__ float scv[256];
    __shared__ float sv[4][64];
    const int tid = threadIdx.x, bi = blockIdx.x;
    const int hb = bi >> 1;
    if (tid < 32){
        float S = 0.f;
        for (int b = tid; b < GRIDA; b += 32) S += g_spart[b*8 + hb];
        S = wred(S);
        if (tid == 0) sS = S;
    }
    const int idx = bi*256 + tid;                 // = hb*512 + c
    float a = 0.f;
    #pragma unroll 8
    for (int b = 0; b < GRIDA; b++) a += g_wpart[(size_t)b*4096 + idx];
    __syncthreads();
    scv[tid] = a / sS;
    __syncthreads();
    const int d = tid & 63, isub = tid >> 6;
    const int i0 = (bi & 1)*256;
    float pv = 0.f;
    #pragma unroll 8
    for (int ii = 0; ii < 64; ii++){
        int i = i0 + isub*64 + ii;
        pv += scv[isub*64+ii]*g_Wcv[(size_t)i*DIM + hb*64 + d];
    }
    sv[isub][d] = pv;
    __syncthreads();
    if (tid < 64)
        atomicAdd(&g_x[256 + hb*64 + tid],
                  sv[0][tid]+sv[1][tid]+sv[2][tid]+sv[3][tid]);
}

// GRU matvecs
__global__ void s5_gru(const float* __restrict__ W_hh, int p){
    const int warp = threadIdx.x >> 5, lane = threadIdx.x & 31;
    const int gw = blockIdx.x*8 + warp, nw = gridDim.x*8;
    for (int r = gw; r < 3072; r += nw){
        float a = 0.f;
        if (r < 1536){
            const float4* W = (const float4*)(g_Wih2 + (size_t)r*XDIM);
            const float4* X = (const float4*)g_x;
            #pragma unroll
            for (int k = 0; k < 6; k++){
                float4 w = W[lane + 32*k], x = X[lane + 32*k];
                a += w.x*x.x + w.y*x.y + w.z*x.z + w.w*x.w;
            }
            a = wred(a);
            if (lane == 0) g_ihh[r] = a + g_bih2[r];
        } else {
            int rr = r - 1536;
            const float4* W = (const float4*)(W_hh + (size_t)rr*DIM);
            const float4* H = (const float4*)g_h[p];
            #pragma unroll
            for (int k = 0; k < 4; k++){
                float4 w = W[lane + 32*k], h = H[lane + 32*k];
                a += w.x*h.x + w.y*h.y + w.z*h.z + w.w*h.w;
            }
            a = wred(a);
            if (lane == 0) g_ihh[r] = a;
        }
    }
}

// gates + heads + output. grid 16 x 256.
__global__ void s6_fin(int p, int step, float* __restrict__ out,
                       const float* __restrict__ b_hn,
                       const float* __restrict__ W_attr, const float* __restrict__ b_attr,
                       const float* __restrict__ W_conf, const float* __restrict__ b_conf){
    __shared__ __align__(16) float hn[DIM];
    const int tid = threadIdx.x;
    for (int j = tid; j < DIM; j += 256){
        float ihr = g_ihh[j],      ihz = g_ihh[512+j],  ihn = g_ihh[1024+j];
        float hhr = g_ihh[1536+j], hhz = g_ihh[2048+j], hhn = g_ihh[2560+j];
        float r = 1.0f/(1.0f + expf(-(ihr + hhr)));
        float z = 1.0f/(1.0f + expf(-(ihz + hhz)));
        float nn = tanhf(ihn + r*(hhn + b_hn[j]));
        float h = (1.0f - z)*nn + z*g_h[p][j];
        hn[j] = h;
        if (blockIdx.x == 0) g_h[1-p][j] = h;
    }
    __syncthreads();
    const int warp = tid >> 5, lane = tid & 31;
    const int gw = blockIdx.x*8 + warp;
    const float4* H4 = (const float4*)hn;
    float4 hv[4];
    #pragma unroll
    for (int k = 0; k < 4; k++) hv[k] = H4[lane + 32*k];
    #pragma unroll
    for (int rr = 0; rr < 2; rr++){
        int row = gw*2 + rr;
        const float4* W = (const float4*)(W_attr + (size_t)row*DIM);
        float a = 0.f;
        #pragma unroll
        for (int k = 0; k < 4; k++){
            float4 w = W[lane + 32*k];
            a += w.x*hv[k].x + w.y*hv[k].y + w.z*hv[k].z + w.w*hv[k].w;
        }
        a = wred(a);
        if (lane == 0){
            float v = a + b_attr[row];
            out[step*ATTR + row] = v;
            g_x[row] = v;
        }
    }
    if (gw == 0){
        const float4* W = (const float4*)W_conf;
        float a = 0.f;
        #pragma unroll
        for (int k = 0; k < 4; k++){
            float4 w = W[lane + 32*k];
            a += w.x*hv[k].x + w.y*hv[k].y + w.z*hv[k].z + w.w*hv[k].w;
        }
        a = wred(a);
        if (lane == 0)
            out[KSTEPS*ATTR + step] = 1.0f/(1.0f + expf(-(a + b_conf[0])));
    }
}

// ------------------------------- launch -----------------------------------
extern "C" void kernel_launch(void* const* d_in, const int* in_sizes, int n_in,
                              void* d_out, int out_size){
    const float* F      = (const float*)d_in[0];
    const float* Wctx   = (const float*)d_in[1];
    const float* bctx   = (const float*)d_in[2];
    const float* Wq     = (const float*)d_in[3];
    const float* bq     = (const float*)d_in[4];
    const float* Wk     = (const float*)d_in[5];
    // d_in[6] = bk : softmax-invariant, unused
    const float* Wv     = (const float*)d_in[7];
    const float* bv     = (const float*)d_in[8];
    const float* Wo     = (const float*)d_in[9];
    const float* bo     = (const float*)d_in[10];
    const float* W_ih   = (const float*)d_in[11];
    const float* W_hh   = (const float*)d_in[12];
    const float* b_ih   = (const float*)d_in[13];
    const float* b_hn   = (const float*)d_in[14];
    const float* start  = (const float*)d_in[15];
    const float* W_attr = (const float*)d_in[16];
    const float* b_attr = (const float*)d_in[17];
    const float* W_conf = (const float*)d_in[18];
    const float* b_conf = (const float*)d_in[19];
    float* out = (float*)d_out;

    p1c<<<1024, 256>>>((const float4*)F);                              // 0
    p2 <<<dim3(16,16,3), dim3(32,8)>>>(Wctx, Wk, Wv);                  // 1
    pAB<<<dim3(16,24,9), 256>>>(Wq, W_ih, Wo);                         // 2
    p4v<<<24, 256>>>(Wctx, bctx, bq, Wv, bv);                          // 3
    p4y<<<153, 256>>>(W_ih, b_ih, bo, start);                          // 4

    for (int step = 0; step < KSTEPS; step++){
        int p = step & 1;
        sA  <<<GRIDA, 512>>>();                                        // 5 on step 0 -> ncu
        s3c <<<16, 256>>>();
        s5_gru<<<96, 256>>>(W_hh, p);
        s6_fin<<<16, 256>>>(p, step, out, b_hn, W_attr, b_attr, W_conf, b_conf);
        if (step + 1 < KSTEPS) s1_u<<<128, 256>>>(1 - p);
    }
}

// round 9
// speedup vs baseline: 1.4912x; 1.1828x over previous
#include <cuda_runtime.h>
#include <cuda_bf16.h>
#include <math.h>

#define NFR    65536
#define DIM    512
#define HEADS  8
#define ATTR   256
#define XDIM   768
#define KSTEPS 16
#define SCALE  0.125f
#define NSTREAM 296
#define GRIDA  148
#define ROWSTRIDE 592
#define ESHIFT 10.0f         // constant logit shift (exactly softmax-invariant)

// ------------------------- static device scratch -------------------------
__device__ __align__(16) __nv_bfloat16 g_Fh[NFR*DIM];    // bf16 frames (64MB)
__device__ __align__(16) float g_WckT[DIM*DIM];          // scale*(W_ctx@Wk)^T [o][i]
__device__ __align__(16) float g_Wcv [DIM*DIM];          // W_ctx@Wv [i][o]
__device__ __align__(16) float g_A[HEADS*DIM*DIM];       // A_h = WckT_h @ Wq_h^T (8MB)
__device__ __align__(16) float g_Wih2[1536*XDIM];        // [W_ih[:,:256] | W_ih[:,256:]@Wo^T]
__device__ __align__(16) float g_bih2[1536];
__device__ __align__(16) float g_cvec[HEADS*DIM];
__device__ __align__(16) float g_cspart[1024*DIM];       // per-block colsum partials
__device__ __align__(16) float g_colsum[DIM];
__device__ __align__(16) float g_bvp[DIM];
__device__ __align__(16) float g_h[2][DIM];
__device__ __align__(16) float g_u[HEADS*DIM];           // [h][i]
__device__ __align__(16) float g_x[XDIM];                // [a_prev(256); vraw(512)]
__device__ __align__(16) float g_ihh[3072];
__device__ __align__(16) float g_wpart[GRIDA*4096];      // per-block weighted sums [b][h*512+c]
__device__ float g_spart[GRIDA*HEADS];

__device__ __forceinline__ float wred(float a){
    #pragma unroll
    for (int o = 16; o; o >>= 1) a += __shfl_xor_sync(0xffffffffu, a, o);
    return a;
}
// ---- packed fp32 (f32x2) helpers ----
typedef unsigned long long ull;
#define FMA2(d,a,b) asm("fma.rn.f32x2 %0, %1, %2, %0;" : "+l"(d) : "l"(a), "l"(b))
__device__ __forceinline__ ull fpack(float a, float b){
    ull r; asm("mov.b64 %0, {%1, %2};" : "=l"(r) : "f"(a), "f"(b)); return r;
}
__device__ __forceinline__ ull bfp(unsigned w){
    unsigned lo = w << 16, hi = w & 0xffff0000u;
    ull r; asm("mov.b64 %0, {%1, %2};" : "=l"(r) : "r"(lo), "r"(hi)); return r;
}
__device__ __forceinline__ float2 funp(ull v){
    float x, y; asm("mov.b64 {%0, %1}, %2;" : "=f"(x), "=f"(y) : "l"(v));
    return make_float2(x, y);
}

// ------------------------------ setup ------------------------------------
// F -> bf16 + per-block colsum partials. grid 1024 x 256.
__global__ void p1c(const float4* __restrict__ F4){
    const int tid = threadIdx.x, col = tid & 127, rh = tid >> 7;
    const int r0 = blockIdx.x*64;
    float4 acc = make_float4(0.f,0.f,0.f,0.f);
    uint2* out = (uint2*)g_Fh;
    for (int i = 0; i < 32; i++){
        size_t row = r0 + i*2 + rh;
        float4 f = F4[row*128 + col];
        acc.x += f.x; acc.y += f.y; acc.z += f.z; acc.w += f.w;
        uint2 pk;
        pk.x = ((unsigned)__bfloat16_as_ushort(__float2bfloat16_rn(f.y)) << 16)
             |  (unsigned)__bfloat16_as_ushort(__float2bfloat16_rn(f.x));
        pk.y = ((unsigned)__bfloat16_as_ushort(__float2bfloat16_rn(f.w)) << 16)
             |  (unsigned)__bfloat16_as_ushort(__float2bfloat16_rn(f.z));
        out[row*128 + col] = pk;
    }
    __shared__ float cs[512];
    if (rh == 0){
        cs[col*4+0]=acc.x; cs[col*4+1]=acc.y; cs[col*4+2]=acc.z; cs[col*4+3]=acc.w;
    }
    __syncthreads();
    if (rh == 1){
        size_t b = (size_t)blockIdx.x*512 + col*4;
        g_cspart[b+0] = cs[col*4+0]+acc.x;
        g_cspart[b+1] = cs[col*4+1]+acc.y;
        g_cspart[b+2] = cs[col*4+2]+acc.z;
        g_cspart[b+3] = cs[col*4+3]+acc.w;
    }
}

// 64x64-tile GEMMs: z=0 WckT = scale*(Wctx@Wk)^T ; z=1 Wcv = Wctx@Wv ; z=2 colsum
__global__ __launch_bounds__(256) void p2(const float* __restrict__ Wctx,
                                          const float* __restrict__ Wk,
                                          const float* __restrict__ Wv){
    const int tid = threadIdx.x;
    if (blockIdx.z == 2){
        const int cb = blockIdx.y*8 + blockIdx.x;
        if (cb >= 16) return;
        const int col = cb*32 + (tid & 31), seg = tid >> 5;
        float a = 0.f;
        #pragma unroll 8
        for (int p = seg*128; p < seg*128+128; p++) a += g_cspart[(size_t)p*512 + col];
        __shared__ float sr[8][33];
        sr[seg][tid & 31] = a;
        __syncthreads();
        if (tid < 32){
            float s2 = 0.f;
            #pragma unroll
            for (int q = 0; q < 8; q++) s2 += sr[q][tid];
            g_colsum[cb*32 + tid] = s2;
        }
        return;
    }
    __shared__ float sA[64][33];
    __shared__ float sB[32][65];
    const float* B = blockIdx.z ? Wv : Wk;
    const int i0 = blockIdx.y*64, j0 = blockIdx.x*64;
    const int tx = tid & 15, ty = tid >> 4;
    float acc[4][4];
    #pragma unroll
    for (int a = 0; a < 4; a++)
        #pragma unroll
        for (int b = 0; b < 4; b++) acc[a][b] = 0.f;
    for (int m0 = 0; m0 < DIM; m0 += 32){
        #pragma unroll
        for (int q = 0; q < 2; q++){
            int e = tid + q*256;
            int r = e >> 3, c = (e & 7)*4;
            float4 va = *(const float4*)(Wctx + (size_t)(i0+r)*DIM + m0 + c);
            sA[r][c+0]=va.x; sA[r][c+1]=va.y; sA[r][c+2]=va.z; sA[r][c+3]=va.w;
            int rb = e >> 4, cb2 = (e & 15)*4;
            float4 vb = *(const float4*)(B + (size_t)(m0+rb)*DIM + j0 + cb2);
            sB[rb][cb2+0]=vb.x; sB[rb][cb2+1]=vb.y; sB[rb][cb2+2]=vb.z; sB[rb][cb2+3]=vb.w;
        }
        __syncthreads();
        #pragma unroll
        for (int m = 0; m < 32; m++){
            float a4[4], b4[4];
            #pragma unroll
            for (int k = 0; k < 4; k++){ a4[k] = sA[ty*4+k][m]; b4[k] = sB[m][tx*4+k]; }
            #pragma unroll
            for (int a = 0; a < 4; a++)
                #pragma unroll
                for (int b = 0; b < 4; b++) acc[a][b] += a4[a]*b4[b];
        }
        __syncthreads();
    }
    if (blockIdx.z){
        #pragma unroll
        for (int a = 0; a < 4; a++)
            *(float4*)(g_Wcv + (size_t)(i0+ty*4+a)*DIM + j0 + tx*4) =
                make_float4(acc[a][0], acc[a][1], acc[a][2], acc[a][3]);
    } else {
        #pragma unroll
        for (int a = 0; a < 4; a++)
            #pragma unroll
            for (int b = 0; b < 4; b++)
                g_WckT[(size_t)(j0+tx*4+b)*DIM + i0+ty*4+a] = SCALE*acc[a][b];
    }
}

// z<8: A_h build ; z=8: Wih2 build ; z=9: vectors (bvp, h0, cvec)
__global__ __launch_bounds__(256) void pAB(const float* __restrict__ Wq,
                                           const float* __restrict__ W_ih,
                                           const float* __restrict__ Wo,
                                           const float* __restrict__ Wctx,
                                           const float* __restrict__ bctx,
                                           const float* __restrict__ bq,
                                           const float* __restrict__ Wv,
                                           const float* __restrict__ bv){
    const int tid = threadIdx.x;
    const int z = blockIdx.z;
    if (z < 8){
        if (blockIdx.y >= 16) return;
        __shared__ float sA_[32][65];
        __shared__ float sB_[32][65];
        const int h = z, i0 = blockIdx.y*32, j0 = blockIdx.x*32;
        for (int e = tid; e < 2048; e += 256){
            int r = e & 31, d = e >> 5;
            sA_[r][d] = g_WckT[(size_t)(h*64+d)*DIM + i0 + r];
        }
        for (int e = tid; e < 2048; e += 256){
            int rj = e >> 6, d = e & 63;
            sB_[rj][d] = Wq[(size_t)(j0+rj)*DIM + h*64 + d];
        }
        __syncthreads();
        const int tx = tid & 31, ty = tid >> 5;
        float acc[4] = {0.f,0.f,0.f,0.f};
        #pragma unroll 8
        for (int d = 0; d < 64; d++){
            float bb = sB_[tx][d];
            #pragma unroll
            for (int k = 0; k < 4; k++) acc[k] += sA_[ty+8*k][d]*bb;
        }
        #pragma unroll
        for (int k = 0; k < 4; k++)
            g_A[(size_t)(h*DIM + i0+ty+8*k)*DIM + j0+tx] = acc[k];
    } else if (z == 8){
        const int i0 = blockIdx.y*64;
        if (blockIdx.x < 8){
            __shared__ float sA[64][33];
            __shared__ float sB[64][33];
            const int j0 = blockIdx.x*64;
            const int tx = tid & 15, ty = tid >> 4;
            float acc[4][4];
            #pragma unroll
            for (int a = 0; a < 4; a++)
                #pragma unroll
                for (int b = 0; b < 4; b++) acc[a][b] = 0.f;
            for (int m0 = 0; m0 < DIM; m0 += 32){
                #pragma unroll
                for (int q = 0; q < 2; q++){
                    int e = tid + q*256, r = e >> 3, c = e & 7;
                    float4 va = *(const float4*)(W_ih + (size_t)(i0+r)*XDIM + 256 + m0 + c*4);
                    sA[r][c*4+0]=va.x; sA[r][c*4+1]=va.y; sA[r][c*4+2]=va.z; sA[r][c*4+3]=va.w;
                    float4 vb = *(const float4*)(Wo + (size_t)(j0+r)*DIM + m0 + c*4);
                    sB[r][c*4+0]=vb.x; sB[r][c*4+1]=vb.y; sB[r][c*4+2]=vb.z; sB[r][c*4+3]=vb.w;
                }
                __syncthreads();
                #pragma unroll
                for (int m = 0; m < 32; m++){
                    float a4[4], b4[4];
                    #pragma unroll
                    for (int k = 0; k < 4; k++){ a4[k] = sA[ty*4+k][m]; b4[k] = sB[tx*4+k][m]; }
                    #pragma unroll
                    for (int a = 0; a < 4; a++)
                        #pragma unroll
                        for (int b = 0; b < 4; b++) acc[a][b] += a4[a]*b4[b];
                }
                __syncthreads();
            }
            #pragma unroll
            for (int a = 0; a < 4; a++){
                float4 v = make_float4(acc[a][0], acc[a][1], acc[a][2], acc[a][3]);
                *(float4*)(g_Wih2 + (size_t)(i0+ty*4+a)*XDIM + 256 + j0 + tx*4) = v;
            }
        } else if (blockIdx.x < 12){
            const int c0 = (blockIdx.x-8)*64;
            for (int e = tid; e < 64*16; e += 256){
                int r = e >> 4, c = e & 15;
                *(float4*)(g_Wih2 + (size_t)(i0+r)*XDIM + c0 + c*4) =
                    *(const float4*)(W_ih + (size_t)(i0+r)*XDIM + c0 + c*4);
            }
        }
    } else {
        // z == 9 : vectors (old p4v). Use blockIdx.y as b (0..23), blockIdx.x == 0.
        if (blockIdx.x != 0) return;
        const int b = blockIdx.y;
        __shared__ float sp[4][64];
        const int tc = tid & 63, pc = tid >> 6;
        if (b < 8){
            const int t = b*64 + tc;
            float a = 0.f;
            #pragma unroll 4
            for (int i = pc*128; i < pc*128+128; i++) a += bctx[i]*Wv[(size_t)i*DIM + t];
            sp[pc][tc] = a;
            __syncthreads();
            if (tid < 64)
                g_bvp[b*64+tid] = sp[0][tid]+sp[1][tid]+sp[2][tid]+sp[3][tid] + bv[b*64+tid];
        } else if (b < 16){
            const int t = (b-8)*64 + tc;
            float a = 0.f;
            #pragma unroll 4
            for (int i = pc*128; i < pc*128+128; i++) a += g_colsum[i]*Wctx[(size_t)i*DIM + t];
            sp[pc][tc] = a;
            __syncthreads();
            if (tid < 64)
                g_h[0][(b-8)*64+tid] = (sp[0][tid]+sp[1][tid]+sp[2][tid]+sp[3][tid])*(1.0f/(float)NFR)
                                       + bctx[(b-8)*64+tid];
        } else {
            const int h = b - 16;
            #pragma unroll
            for (int rr = 0; rr < 2; rr++){
                int i = rr*256 + tid;
                float s = 0.f;
                #pragma unroll 8
                for (int d = 0; d < 64; d++)
                    s += g_WckT[(size_t)(h*64+d)*DIM + i]*bq[h*64+d];
                g_cvec[h*DIM + i] = s;
            }
        }
    }
}

// shared u-matvec body: u = A@h + cvec, 4 rows/warp over 128 virtual blocks
__device__ __forceinline__ void u_body(int bx, int tid, const float4* __restrict__ H4){
    const int w = tid >> 5, lane = tid & 31;
    if (bx == 0){ g_x[256+tid] = 0.f; g_x[512+tid] = 0.f; }
    float4 hv[4];
    #pragma unroll
    for (int k = 0; k < 4; k++) hv[k] = H4[lane + 32*k];
    const int gw = bx*8 + w;
    #pragma unroll
    for (int rr = 0; rr < 4; rr++){
        int r = gw + rr*1024;
        const float4* A4 = (const float4*)(g_A + (size_t)r*DIM);
        float a = 0.f;
        #pragma unroll
        for (int k = 0; k < 4; k++){
            float4 av = A4[lane + 32*k];
            a += av.x*hv[k].x + av.y*hv[k].y + av.z*hv[k].z + av.w*hv[k].w;
        }
        a = wred(a);
        if (lane == 0) g_u[r] = a + g_cvec[r];
    }
}

// b<24: bih2 ; b=24: start copy ; b>=25: pre-loop u = A@h0 + cvec. grid 153.
__global__ void p4y(const float* __restrict__ W_ih, const float* __restrict__ b_ih,
                    const float* __restrict__ bo,   const float* __restrict__ start){
    const int b = blockIdx.x, tid = threadIdx.x;
    if (b >= 25){ u_body(b-25, tid, (const float4*)g_h[0]); return; }
    if (b == 24){
        if (tid < ATTR) g_x[tid] = start[tid];
        return;
    }
    __shared__ float sbvp[DIM];
    __shared__ float sbo[DIM];
    #pragma unroll
    for (int rr = 0; rr < 2; rr++){
        int t = rr*256 + tid;
        sbvp[t] = g_bvp[t];
        sbo[t]  = bo[t];
    }
    __syncthreads();
    const int w = tid >> 5, lane = tid & 31;
    const int r0 = b*64;
    for (int rr = w; rr < 64; rr += 8){
        int r = r0 + rr;
        const float4* W2 = (const float4*)(g_Wih2 + (size_t)r*XDIM + 256);
        const float4* WI = (const float4*)(W_ih + (size_t)r*XDIM + 256);
        float a = 0.f;
        #pragma unroll
        for (int k = 0; k < 4; k++){
            float4 w2 = W2[lane+32*k];
            float4 wi = WI[lane+32*k];
            int kb = (lane+32*k)*4;
            a += w2.x*sbvp[kb+0] + w2.y*sbvp[kb+1] + w2.z*sbvp[kb+2] + w2.w*sbvp[kb+3];
            a += wi.x*sbo[kb+0]  + wi.y*sbo[kb+1]  + wi.z*sbo[kb+2]  + wi.w*sbo[kb+3];
        }
        a = wred(a);
        if (lane == 0) g_bih2[r] = a + b_ih[r];
    }
}

// ----------------------------- per-step ----------------------------------
// Fused one-pass attention, no-max softmax. grid 148 x 512.
__global__ void __launch_bounds__(512,1) sA(){
    const int tid = threadIdx.x, w = tid >> 5, lane = tid & 31;
    const int head = w & 7, grp = w >> 3;
    const int stream = blockIdx.x*2 + grp;          // 0..295

    ull u[8];
    {
        const float4* U4 = (const float4*)(g_u + head*DIM);
        #pragma unroll
        for (int jj = 0; jj < 2; jj++){
            float4 va = U4[2*lane + 64*jj];
            float4 vb = U4[2*lane + 64*jj + 1];
            u[4*jj+0] = fpack(va.x, va.y);
            u[4*jj+1] = fpack(va.z, va.w);
            u[4*jj+2] = fpack(vb.x, vb.y);
            u[4*jj+3] = fpack(vb.z, vb.w);
        }
    }
    ull acc[8];
    #pragma unroll
    for (int j = 0; j < 8; j++) acc[j] = 0ull;
    float s = 0.f;

    const uint4* Fq = (const uint4*)g_Fh;
    #pragma unroll 2
    for (int n = stream*2; n < NFR; n += ROWSTRIDE){
        const size_t q0 = (size_t)n*64, q1 = q0 + 64;
        uint4 ra = Fq[q0 + lane], rb = Fq[q0 + lane + 32];
        uint4 rc = Fq[q1 + lane], rd = Fq[q1 + lane + 32];
        ull f0 = bfp(ra.x), f1 = bfp(ra.y), f2 = bfp(ra.z), f3 = bfp(ra.w);
        ull f4 = bfp(rb.x), f5 = bfp(rb.y), f6 = bfp(rb.z), f7 = bfp(rb.w);
        ull g0 = bfp(rc.x), g1 = bfp(rc.y), g2 = bfp(rc.z), g3 = bfp(rc.w);
        ull g4 = bfp(rd.x), g5 = bfp(rd.y), g6 = bfp(rd.z), g7 = bfp(rd.w);
        ull l0 = 0ull, l1 = 0ull, l2 = 0ull, l3 = 0ull;
        FMA2(l0, f0, u[0]); FMA2(l1, f1, u[1]); FMA2(l2, g0, u[0]); FMA2(l3, g1, u[1]);
        FMA2(l0, f2, u[2]); FMA2(l1, f3, u[3]); FMA2(l2, g2, u[2]); FMA2(l3, g3, u[3]);
        FMA2(l0, f4, u[4]); FMA2(l1, f5, u[5]); FMA2(l2, g4, u[4]); FMA2(l3, g5, u[5]);
        FMA2(l0, f6, u[6]); FMA2(l1, f7, u[7]); FMA2(l2, g6, u[6]); FMA2(l3, g7, u[7]);
        float2 pa = funp(l0), pb = funp(l1), pc = funp(l2), pd = funp(l3);
        float la = (pa.x + pb.x) + (pa.y + pb.y);
        float lb = (pc.x + pd.x) + (pc.y + pd.y);
        #pragma unroll
        for (int o = 16; o; o >>= 1){
            la += __shfl_xor_sync(0xffffffffu, la, o);
            lb += __shfl_xor_sync(0xffffffffu, lb, o);
        }
        float e1 = __expf(la - ESHIFT);
        float e2 = __expf(lb - ESHIFT);
        s += e1 + e2;
        ull ee1 = fpack(e1, e1), ee2 = fpack(e2, e2);
        FMA2(acc[0], ee1, f0); FMA2(acc[1], ee1, f1);
        FMA2(acc[2], ee1, f2); FMA2(acc[3], ee1, f3);
        FMA2(acc[4], ee1, f4); FMA2(acc[5], ee1, f5);
        FMA2(acc[6], ee1, f6); FMA2(acc[7], ee1, f7);
        FMA2(acc[0], ee2, g0); FMA2(acc[1], ee2, g1);
        FMA2(acc[2], ee2, g2); FMA2(acc[3], ee2, g3);
        FMA2(acc[4], ee2, g4); FMA2(acc[5], ee2, g5);
        FMA2(acc[6], ee2, g6); FMA2(acc[7], ee2, g7);
    }

    // pair-combine (warp w with w+8, same head): plain sums, coalesced store
    __shared__ float ss_[16];
    __shared__ __align__(16) float sacc[16*512];
    if (lane == 0) ss_[w] = s;
    float* base = sacc + w*512;
    #pragma unroll
    for (int jj = 0; jj < 2; jj++){
        float2 v0 = funp(acc[4*jj+0]), v1 = funp(acc[4*jj+1]);
        float2 v2 = funp(acc[4*jj+2]), v3 = funp(acc[4*jj+3]);
        *(float4*)&base[8*lane + 256*jj]     = make_float4(v0.x, v0.y, v1.x, v1.y);
        *(float4*)&base[8*lane + 256*jj + 4] = make_float4(v2.x, v2.y, v3.x, v3.y);
    }
    __syncthreads();
    if (w < 8){
        const float* b1 = sacc + w*512;
        const float* b2 = sacc + (w+8)*512;
        float* op = g_wpart + (size_t)blockIdx.x*4096 + w*512;
        #pragma unroll
        for (int t = lane*4; t < 512; t += 128){
            float4 x1 = *(const float4*)&b1[t];
            float4 x2 = *(const float4*)&b2[t];
            *(float4*)&op[t] = make_float4(x1.x+x2.x, x1.y+x2.y, x1.z+x2.z, x1.w+x2.w);
        }
        if (lane == 0) g_spart[blockIdx.x*8 + w] = ss_[w] + ss_[w+8];
    }
}

// blocks 0..15: combine partials -> c ; vraw += c@Wcv (into g_x[256:768])
// blocks 16..63: hh = W_hh @ h[p]  -> g_ihh[1536:3072]   (x-independent)
__global__ void s3h(const float* __restrict__ W_hh, int p){
    const int tid = threadIdx.x, bi = blockIdx.x;
    if (bi >= 16){
        const int w = tid >> 5, lane = tid & 31;
        const int gw2 = (bi-16)*8 + w;                // 0..383
        const float4* H = (const float4*)g_h[p];
        float4 hv[4];
        #pragma unroll
        for (int k = 0; k < 4; k++) hv[k] = H[lane + 32*k];
        #pragma unroll
        for (int rr = 0; rr < 4; rr++){
            int r = gw2 + rr*384;                     // 0..1535
            const float4* W = (const float4*)(W_hh + (size_t)r*DIM);
            float a = 0.f;
            #pragma unroll
            for (int k = 0; k < 4; k++){
                float4 w4 = W[lane + 32*k];
                a += w4.x*hv[k].x + w4.y*hv[k].y + w4.z*hv[k].z + w4.w*hv[k].w;
            }
            a = wred(a);
            if (lane == 0) g_ihh[1536 + r] = a;
        }
        return;
    }
    __shared__ float sS;
    __shared__ float scv[256];
    __shared__ float sv[4][64];
    const int hb = bi >> 1;
    if (tid < 32){
        float S = 0.f;
        for (int b = tid; b < GRIDA; b += 32) S += g_spart[b*8 + hb];
        S = wred(S);
        if (tid == 0) sS = S;
    }
    const int idx = bi*256 + tid;                 // = hb*512 + c
    float a = 0.f;
    #pragma unroll 8
    for (int b = 0; b < GRIDA; b++) a += g_wpart[(size_t)b*4096 + idx];
    __syncthreads();
    scv[tid] = a / sS;
    __syncthreads();
    const int d = tid & 63, isub = tid >> 6;
    const int i0 = (bi & 1)*256;
    float pv = 0.f;
    #pragma unroll 8
    for (int ii = 0; ii < 64; ii++){
        int i = i0 + isub*64 + ii;
        pv += scv[isub*64+ii]*g_Wcv[(size_t)i*DIM + hb*64 + d];
    }
    sv[isub][d] = pv;
    __syncthreads();
    if (tid < 64)
        atomicAdd(&g_x[256 + hb*64 + tid],
                  sv[0][tid]+sv[1][tid]+sv[2][tid]+sv[3][tid]);
}

// ih = Wih2@[a;v] + bih2 -> g_ihh[0:1536). grid 64 x 256.
__global__ void s5i(){
    const int w = threadIdx.x >> 5, lane = threadIdx.x & 31;
    const int gw = blockIdx.x*8 + w;                  // 0..511
    const float4* X = (const float4*)g_x;
    float4 xv[6];
    #pragma unroll
    for (int k = 0; k < 6; k++) xv[k] = X[lane + 32*k];
    #pragma unroll
    for (int rr = 0; rr < 3; rr++){
        int r = gw + rr*512;
        const float4* W = (const float4*)(g_Wih2 + (size_t)r*XDIM);
        float a = 0.f;
        #pragma unroll
        for (int k = 0; k < 6; k++){
            float4 w4 = W[lane + 32*k];
            a += w4.x*xv[k].x + w4.y*xv[k].y + w4.z*xv[k].z + w4.w*xv[k].w;
        }
        a = wred(a);
        if (lane == 0) g_ihh[r] = a + g_bih2[r];
    }
}

// gates + heads + output + u for next step + vraw zero. grid 128 x 256.
__global__ void s6u(int p, int step, float* __restrict__ out,
                    const float* __restrict__ b_hn,
                    const float* __restrict__ W_attr, const float* __restrict__ b_attr,
                    const float* __restrict__ W_conf, const float* __restrict__ b_conf){
    __shared__ __align__(16) float hn[DIM];
    const int tid = threadIdx.x;
    for (int j = tid; j < DIM; j += 256){
        float ihr = g_ihh[j],      ihz = g_ihh[512+j],  ihn = g_ihh[1024+j];
        float hhr = g_ihh[1536+j], hhz = g_ihh[2048+j], hhn = g_ihh[2560+j];
        float r = 1.0f/(1.0f + expf(-(ihr + hhr)));
        float z = 1.0f/(1.0f + expf(-(ihz + hhz)));
        float nn = tanhf(ihn + r*(hhn + b_hn[j]));
        float h = (1.0f - z)*nn + z*g_h[p][j];
        hn[j] = h;
        if (blockIdx.x == 0) g_h[1-p][j] = h;
    }
    __syncthreads();
    const int warp = tid >> 5, lane = tid & 31;
    if (blockIdx.x < 16){
        const int gw = blockIdx.x*8 + warp;           // 0..127
        const float4* H4 = (const float4*)hn;
        float4 hv[4];
        #pragma unroll
        for (int k = 0; k < 4; k++) hv[k] = H4[lane + 32*k];
        #pragma unroll
        for (int rr = 0; rr < 2; rr++){
            int row = gw*2 + rr;
            const float4* W = (const float4*)(W_attr + (size_t)row*DIM);
            float a = 0.f;
            #pragma unroll
            for (int k = 0; k < 4; k++){
                float4 w4 = W[lane + 32*k];
                a += w4.x*hv[k].x + w4.y*hv[k].y + w4.z*hv[k].z + w4.w*hv[k].w;
            }
            a = wred(a);
            if (lane == 0){
                float v = a + b_attr[row];
                out[step*ATTR + row] = v;
                g_x[row] = v;
            }
        }
        if (gw == 0){
            const float4* W = (const float4*)W_conf;
            float a = 0.f;
            #pragma unroll
            for (int k = 0; k < 4; k++){
                float4 w4 = W[lane + 32*k];
                a += w4.x*hv[k].x + w4.y*hv[k].y + w4.z*hv[k].z + w4.w*hv[k].w;
            }
            a = wred(a);
            if (lane == 0)
                out[KSTEPS*ATTR + step] = 1.0f/(1.0f + expf(-(a + b_conf[0])));
        }
    }
    // u' = A@h_new + cvec (all 128 blocks); block 0 zeroes vraw
    u_body(blockIdx.x, tid, (const float4*)hn);
}

// ------------------------------- launch -----------------------------------
extern "C" void kernel_launch(void* const* d_in, const int* in_sizes, int n_in,
                              void* d_out, int out_size){
    const float* F      = (const float*)d_in[0];
    const float* Wctx   = (const float*)d_in[1];
    const float* bctx   = (const float*)d_in[2];
    const float* Wq     = (const float*)d_in[3];
    const float* bq     = (const float*)d_in[4];
    const float* Wk     = (const float*)d_in[5];
    // d_in[6] = bk : softmax-invariant, unused
    const float* Wv     = (const float*)d_in[7];
    const float* bv     = (const float*)d_in[8];
    const float* Wo     = (const float*)d_in[9];
    const float* bo     = (const float*)d_in[10];
    const float* W_ih   = (const float*)d_in[11];
    const float* W_hh   = (const float*)d_in[12];
    const float* b_ih   = (const float*)d_in[13];
    const float* b_hn   = (const float*)d_in[14];
    const float* start  = (const float*)d_in[15];
    const float* W_attr = (const float*)d_in[16];
    const float* b_attr = (const float*)d_in[17];
    const float* W_conf = (const float*)d_in[18];
    const float* b_conf = (const float*)d_in[19];
    float* out = (float*)d_out;

    p1c<<<1024, 256>>>((const float4*)F);
    p2 <<<dim3(8,8,3), 256>>>(Wctx, Wk, Wv);
    pAB<<<dim3(16,24,10), 256>>>(Wq, W_ih, Wo, Wctx, bctx, bq, Wv, bv);
    p4y<<<153, 256>>>(W_ih, b_ih, bo, start);

    for (int step = 0; step < KSTEPS; step++){
        int p = step & 1;
        sA  <<<GRIDA, 512>>>();
        s3h <<<64, 256>>>(W_hh, p);
        s5i <<<64, 256>>>();
        s6u <<<128, 256>>>(p, step, out, b_hn, W_attr, b_attr, W_conf, b_conf);
    }
}